// round 1
// baseline (speedup 1.0000x reference)
#include <cuda_runtime.h>
#include <math.h>

#define BB 2
#define SS 512
#define HH 128
#define AA 7
#define TI 8
#define TJ 32
#define EPSF 1e-5f

// Scratch (no allocations allowed): hvL, hdL, hvR, hdR
__device__ float g_proj[4][BB * SS * HH];
__device__ float g_logits[BB * SS * AA];
__device__ float g_wg[2][HH];
__device__ float g_c[2][2];  // [head][0]=sum(pw*g), [head][1]=sum(pw*b)+pb

__device__ __forceinline__ float tanh_fast(float x) {
    float y;
    asm("tanh.approx.f32 %0, %1;" : "=f"(y) : "f"(x));
    return y;
}

// tanh-approx GeLU: 0.5*x*(1+tanh(0.7978845608*(x + 0.044715*x^3)))
__device__ __forceinline__ float gelu_t(float x) {
    float x2 = x * x;
    float u = x * fmaf(0.7978845608f * 0.044715f, x2, 0.7978845608f);
    float t = tanh_fast(u);
    float xh = 0.5f * x;
    return fmaf(xh, t, xh);
}

// Block reductions for blockDim.x == 128 (4 warps). Safe for back-to-back calls.
__device__ __forceinline__ float blockSum128(float v, float* red) {
#pragma unroll
    for (int o = 16; o; o >>= 1) v += __shfl_xor_sync(0xffffffffu, v, o);
    __syncthreads();
    if ((threadIdx.x & 31) == 0) red[threadIdx.x >> 5] = v;
    __syncthreads();
    return red[0] + red[1] + red[2] + red[3];
}

__device__ __forceinline__ float blockMax128(float v, float* red) {
#pragma unroll
    for (int o = 16; o; o >>= 1) v = fmaxf(v, __shfl_xor_sync(0xffffffffu, v, o));
    __syncthreads();
    if ((threadIdx.x & 31) == 0) red[threadIdx.x >> 5] = v;
    __syncthreads();
    return fmaxf(fmaxf(red[0], red[1]), fmaxf(red[2], red[3]));
}

// K0: fold projection vector + LN affine into wg / c1 / c2 per head.
__global__ void k0_prep(const float* lpw, const float* lg, const float* lb, const float* lpb,
                        const float* rpw, const float* rg, const float* rb, const float* rpb) {
    __shared__ float red[4];
    int head = blockIdx.x;
    const float* pw = head ? rpw : lpw;
    const float* g  = head ? rg  : lg;
    const float* bb = head ? rb  : lb;
    const float* pb = head ? rpb : lpb;
    int h = threadIdx.x;
    float w = pw[h];
    float wg = w * g[h];
    g_wg[head][h] = wg;
    float c1 = blockSum128(wg, red);
    float c2 = blockSum128(w * bb[h], red);
    if (h == 0) {
        g_c[head][0] = c1;
        g_c[head][1] = c2 + pb[0];
    }
}

// K1: per-token projections (4 pointer GEMVs + action GEMV->gelu->LN->logits)
__global__ void k1_token(const float* __restrict__ hid,
                         const float* __restrict__ aw1, const float* __restrict__ ab1,
                         const float* __restrict__ alg, const float* __restrict__ alb,
                         const float* __restrict__ aw2, const float* __restrict__ ab2,
                         const float* __restrict__ lhw, const float* __restrict__ lhb,
                         const float* __restrict__ lew, const float* __restrict__ leb,
                         const float* __restrict__ rhw, const float* __restrict__ rhb,
                         const float* __restrict__ rew, const float* __restrict__ reb) {
    __shared__ float sh[HH];
    __shared__ float sa[HH];
    __shared__ float red[4];
    int t = blockIdx.x;
    int j = threadIdx.x;
    float hj = hid[t * HH + j];
    sh[j] = hj;
    __syncthreads();

    float p0 = lhb[j], p1 = leb[j], p2 = rhb[j], p3 = reb[j], a = ab1[j];
#pragma unroll 4
    for (int k = 0; k < HH; k++) {
        float hk = sh[k];
        p0 = fmaf(hk, lhw[k * HH + j], p0);
        p1 = fmaf(hk, lew[k * HH + j], p1);
        p2 = fmaf(hk, rhw[k * HH + j], p2);
        p3 = fmaf(hk, rew[k * HH + j], p3);
        a  = fmaf(hk, aw1[k * HH + j], a);
    }
    g_proj[0][t * HH + j] = p0;
    g_proj[1][t * HH + j] = p1;
    g_proj[2][t * HH + j] = p2;
    g_proj[3][t * HH + j] = p3;

    float x = gelu_t(a);
    float s0 = blockSum128(x, red);
    float s1 = blockSum128(x * x, red);
    float m = s0 * (1.0f / HH);
    float var = s1 * (1.0f / HH) - m * m;
    float rstd = rsqrtf(var + EPSF);
    float an = fmaf((x - m) * rstd, alg[j], alb[j]);
    sa[j] = an;
    __syncthreads();

    for (int ai = 0; ai < AA; ai++) {
        float part = sa[j] * aw2[j * AA + ai];
        float s = blockSum128(part, red);
        if (j == 0) g_logits[t * AA + ai] = s + ab2[ai];
    }
}

// K2: pointer pair scores. One thread per (i,j) pair, serial H loop.
// block = 256 threads = TI(8) x TJ(32). grid = (1024, B*2)
__global__ __launch_bounds__(256) void k2_scores(float* __restrict__ out) {
    __shared__ float hv_s[TJ * 129];  // pad 129 -> conflict-free (bank = (j+h)%32)
    __shared__ float hd_s[TI * HH];   // broadcast within warp, no pad needed
    __shared__ float wg_s[HH];

    int bh = blockIdx.y;
    int b = bh >> 1, head = bh & 1;
    int iBlk = blockIdx.x >> 4, jBlk = blockIdx.x & 15;
    int i0 = iBlk * TI, j0 = jBlk * TJ;

    const float* hv = g_proj[head * 2 + 0] + b * SS * HH;
    const float* hd = g_proj[head * 2 + 1] + b * SS * HH;

    int tid = threadIdx.x;
    if (tid < HH) wg_s[tid] = g_wg[head][tid];
    for (int idx = tid; idx < TI * HH; idx += 256) hd_s[idx] = hd[i0 * HH + idx];
    for (int idx = tid; idx < TJ * HH; idx += 256) {
        int r = idx >> 7, c = idx & 127;
        hv_s[r * 129 + c] = hv[(j0 + r) * HH + c];
    }
    __syncthreads();

    int jl = tid & 31, il = tid >> 5;
    const float* hdp = &hd_s[il * HH];
    const float* hvp = &hv_s[jl * 129];

    float s0 = 0.f, s1 = 0.f, sd = 0.f;
#pragma unroll 8
    for (int h = 0; h < HH; h++) {
        float x = hdp[h] + hvp[h];
        float gx = gelu_t(x);
        s0 += gx;
        s1 = fmaf(gx, gx, s1);
        sd = fmaf(wg_s[h], gx, sd);
    }
    float m = s0 * (1.0f / HH);
    float var = s1 * (1.0f / HH) - m * m;
    float rstd = rsqrtf(var + EPSF);
    float score = fmaf(rstd, sd - m * g_c[head][0], g_c[head][1]);

    out[BB * SS * AA + head * (BB * SS * SS) + b * (SS * SS) + (i0 + il) * SS + (j0 + jl)] = score;
}

// K3: in-place log-softmax over last dim (length 512) for lefts+rights rows.
__global__ void k3_lsm_rows(float* __restrict__ out) {
    __shared__ float red[4];
    int row = blockIdx.x;  // 0 .. 2*B*S-1
    float* p = out + BB * SS * AA + row * SS;
    int tid = threadIdx.x;
    float v[4];
    float mx = -INFINITY;
#pragma unroll
    for (int k = 0; k < 4; k++) {
        v[k] = p[tid + k * 128];
        mx = fmaxf(mx, v[k]);
    }
    mx = blockMax128(mx, red);
    float s = 0.f;
#pragma unroll
    for (int k = 0; k < 4; k++) s += __expf(v[k] - mx);
    s = blockSum128(s, red);
    float l = mx + logf(s);
#pragma unroll
    for (int k = 0; k < 4; k++) p[tid + k * 128] = v[k] - l;
}

// K4: actions log-softmax over the SEQUENCE dim (axis=1). One block per (b,a).
__global__ void k4_actions(float* __restrict__ out) {
    __shared__ float red[4];
    int ba = blockIdx.x;  // 0..13
    int b = ba / AA, a = ba % AA;
    const float* lg = g_logits + b * SS * AA + a;
    int tid = threadIdx.x;
    float v[4];
    float mx = -INFINITY;
#pragma unroll
    for (int k = 0; k < 4; k++) {
        v[k] = lg[(tid + k * 128) * AA];
        mx = fmaxf(mx, v[k]);
    }
    mx = blockMax128(mx, red);
    float s = 0.f;
#pragma unroll
    for (int k = 0; k < 4; k++) s += __expf(v[k] - mx);
    s = blockSum128(s, red);
    float l = mx + logf(s);
    float* o = out + b * SS * AA + a;
#pragma unroll
    for (int k = 0; k < 4; k++) o[(tid + k * 128) * AA] = v[k] - l;
}

extern "C" void kernel_launch(void* const* d_in, const int* in_sizes, int n_in,
                              void* d_out, int out_size) {
    const float* hiddens = (const float*)d_in[0];
    const float* aw1     = (const float*)d_in[1];
    const float* ab1     = (const float*)d_in[2];
    const float* a_ln_g  = (const float*)d_in[3];
    const float* a_ln_b  = (const float*)d_in[4];
    const float* aw2     = (const float*)d_in[5];
    const float* ab2     = (const float*)d_in[6];
    const float* lhid_w  = (const float*)d_in[7];
    const float* lhid_b  = (const float*)d_in[8];
    const float* lhead_w = (const float*)d_in[9];
    const float* lhead_b = (const float*)d_in[10];
    const float* l_ln_g  = (const float*)d_in[11];
    const float* l_ln_b  = (const float*)d_in[12];
    const float* l_proj_w = (const float*)d_in[13];
    const float* l_proj_b = (const float*)d_in[14];
    const float* rhid_w  = (const float*)d_in[15];
    const float* rhid_b  = (const float*)d_in[16];
    const float* rhead_w = (const float*)d_in[17];
    const float* rhead_b = (const float*)d_in[18];
    const float* r_ln_g  = (const float*)d_in[19];
    const float* r_ln_b  = (const float*)d_in[20];
    const float* r_proj_w = (const float*)d_in[21];
    const float* r_proj_b = (const float*)d_in[22];
    float* out = (float*)d_out;

    k0_prep<<<2, 128>>>(l_proj_w, l_ln_g, l_ln_b, l_proj_b,
                        r_proj_w, r_ln_g, r_ln_b, r_proj_b);
    k1_token<<<BB * SS, 128>>>(hiddens, aw1, ab1, a_ln_g, a_ln_b, aw2, ab2,
                               lhid_w, lhid_b, lhead_w, lhead_b,
                               rhid_w, rhid_b, rhead_w, rhead_b);
    k2_scores<<<dim3(1024, BB * 2), 256>>>(out);
    k3_lsm_rows<<<2 * BB * SS, 128>>>(out);
    k4_actions<<<BB * AA, 128>>>(out);
}

// round 2
// speedup vs baseline: 1.1914x; 1.1914x over previous
#include <cuda_runtime.h>
#include <math.h>

#define BB 2
#define SS 512
#define HH 128
#define AA 7
#define TI 8
#define TJ 32
#define T1 16
#define EPSF 1e-5f

typedef unsigned long long ull;

// Scratch: pointer projections (hvL, hdL, hvR, hdR), action pre-activation, logits
__device__ float g_proj[4][BB * SS * HH];
__device__ float g_act[BB * SS * HH];
__device__ float g_logits[BB * SS * AA];
__device__ float g_wg[2][HH];
__device__ float g_c[2][2];

// ---------------- packed f32x2 helpers (sm_103a) ----------------
__device__ __forceinline__ ull pk(float lo, float hi) {
    ull r; asm("mov.b64 %0, {%1, %2};" : "=l"(r) : "f"(lo), "f"(hi)); return r;
}
__device__ __forceinline__ void upk(ull v, float& lo, float& hi) {
    asm("mov.b64 {%0, %1}, %2;" : "=f"(lo), "=f"(hi) : "l"(v));
}
__device__ __forceinline__ ull add2(ull a, ull b) {
    ull r; asm("add.rn.f32x2 %0, %1, %2;" : "=l"(r) : "l"(a), "l"(b)); return r;
}
__device__ __forceinline__ ull mul2(ull a, ull b) {
    ull r; asm("mul.rn.f32x2 %0, %1, %2;" : "=l"(r) : "l"(a), "l"(b)); return r;
}
__device__ __forceinline__ ull fma2(ull a, ull b, ull c) {
    ull r; asm("fma.rn.f32x2 %0, %1, %2, %3;" : "=l"(r) : "l"(a), "l"(b), "l"(c)); return r;
}

__device__ __forceinline__ float tanh_fast(float x) {
    float y; asm("tanh.approx.f32 %0, %1;" : "=f"(y) : "f"(x)); return y;
}

__device__ __forceinline__ float gelu_t(float x) {
    float x2 = x * x;
    float u = x * fmaf(0.7978845608f * 0.044715f, x2, 0.7978845608f);
    float t = tanh_fast(u);
    float xh = 0.5f * x;
    return fmaf(xh, t, xh);
}

// ---------------- block reductions (blockDim.x == 128) ----------------
__device__ __forceinline__ float blockSum128(float v, float* red) {
#pragma unroll
    for (int o = 16; o; o >>= 1) v += __shfl_xor_sync(0xffffffffu, v, o);
    __syncthreads();
    if ((threadIdx.x & 31) == 0) red[threadIdx.x >> 5] = v;
    __syncthreads();
    return red[0] + red[1] + red[2] + red[3];
}
__device__ __forceinline__ float blockMax128(float v, float* red) {
#pragma unroll
    for (int o = 16; o; o >>= 1) v = fmaxf(v, __shfl_xor_sync(0xffffffffu, v, o));
    __syncthreads();
    if ((threadIdx.x & 31) == 0) red[threadIdx.x >> 5] = v;
    __syncthreads();
    return fmaxf(fmaxf(red[0], red[1]), fmaxf(red[2], red[3]));
}

// K0: fold proj vector + LN affine into wg / constants.
__global__ void k0_prep(const float* lpw, const float* lg, const float* lb, const float* lpb,
                        const float* rpw, const float* rg, const float* rb, const float* rpb) {
    __shared__ float red[4];
    int head = blockIdx.x;
    const float* pw = head ? rpw : lpw;
    const float* g  = head ? rg  : lg;
    const float* bb = head ? rb  : lb;
    const float* pb = head ? rpb : lpb;
    int h = threadIdx.x;
    float w = pw[h];
    float wg = w * g[h];
    g_wg[head][h] = wg;
    float c1 = blockSum128(wg, red);
    float c2 = blockSum128(w * bb[h], red);
    if (h == 0) { g_c[head][0] = c1; g_c[head][1] = c2 + pb[0]; }
}

// K1a: tiled projections. grid=(64, 5): blockIdx.x = token group of 16,
// blockIdx.y = matrix (0..3 pointer, 4 = aw1). Each block reads one 64KB matrix once.
__global__ __launch_bounds__(128) void k1a_proj(
        const float* __restrict__ hid,
        const float* __restrict__ w0, const float* __restrict__ b0,
        const float* __restrict__ w1, const float* __restrict__ b1,
        const float* __restrict__ w2, const float* __restrict__ b2,
        const float* __restrict__ w3, const float* __restrict__ b3,
        const float* __restrict__ w4, const float* __restrict__ b4) {
    __shared__ float sh[HH * 20];  // transposed [h][token], stride 20 (16B-aligned rows)
    int m = blockIdx.y;
    const float* W; const float* B; float* O;
    if      (m == 0) { W = w0; B = b0; O = g_proj[0]; }
    else if (m == 1) { W = w1; B = b1; O = g_proj[1]; }
    else if (m == 2) { W = w2; B = b2; O = g_proj[2]; }
    else if (m == 3) { W = w3; B = b3; O = g_proj[3]; }
    else             { W = w4; B = b4; O = g_act; }

    int t0 = blockIdx.x * T1;
    int tid = threadIdx.x;
    for (int idx = tid; idx < T1 * HH; idx += 128) {
        int t = idx >> 7, c = idx & 127;
        sh[c * 20 + t] = hid[(t0 + t) * HH + c];
    }
    __syncthreads();

    int j = tid;
    float bj = B[j];
    float acc[T1];
#pragma unroll
    for (int t = 0; t < T1; t++) acc[t] = bj;

#pragma unroll 4
    for (int k = 0; k < HH; k++) {
        float w = W[k * HH + j];
        const float4* hp = (const float4*)&sh[k * 20];
        float4 h0 = hp[0], h1 = hp[1], h2 = hp[2], h3 = hp[3];
        acc[0]  = fmaf(h0.x, w, acc[0]);  acc[1]  = fmaf(h0.y, w, acc[1]);
        acc[2]  = fmaf(h0.z, w, acc[2]);  acc[3]  = fmaf(h0.w, w, acc[3]);
        acc[4]  = fmaf(h1.x, w, acc[4]);  acc[5]  = fmaf(h1.y, w, acc[5]);
        acc[6]  = fmaf(h1.z, w, acc[6]);  acc[7]  = fmaf(h1.w, w, acc[7]);
        acc[8]  = fmaf(h2.x, w, acc[8]);  acc[9]  = fmaf(h2.y, w, acc[9]);
        acc[10] = fmaf(h2.z, w, acc[10]); acc[11] = fmaf(h2.w, w, acc[11]);
        acc[12] = fmaf(h3.x, w, acc[12]); acc[13] = fmaf(h3.y, w, acc[13]);
        acc[14] = fmaf(h3.z, w, acc[14]); acc[15] = fmaf(h3.w, w, acc[15]);
    }
#pragma unroll
    for (int t = 0; t < T1; t++) O[(t0 + t) * HH + j] = acc[t];
}

// K1b: action tail: gelu -> LN -> 7 logits. One block per token.
__global__ __launch_bounds__(128) void k1b_action(
        const float* __restrict__ alg, const float* __restrict__ alb,
        const float* __restrict__ aw2, const float* __restrict__ ab2) {
    __shared__ float sa[HH];
    __shared__ float red[4];
    int t = blockIdx.x;
    int tid = threadIdx.x;
    float x = gelu_t(g_act[t * HH + tid]);
    float s0 = blockSum128(x, red);
    float s1 = blockSum128(x * x, red);
    float m = s0 * (1.0f / HH);
    float var = s1 * (1.0f / HH) - m * m;
    float rstd = rsqrtf(var + EPSF);
    sa[tid] = fmaf((x - m) * rstd, alg[tid], alb[tid]);
    __syncthreads();

    int w = tid >> 5, l = tid & 31;
    for (int a = w; a < AA; a += 4) {
        float s = 0.f;
#pragma unroll
        for (int q = 0; q < 4; q++) {
            int jj = l + 32 * q;
            s = fmaf(sa[jj], aw2[jj * AA + a], s);
        }
#pragma unroll
        for (int o = 16; o; o >>= 1) s += __shfl_xor_sync(0xffffffffu, s, o);
        if (l == 0) g_logits[t * AA + a] = s + ab2[a];
    }
}

// K2: pointer pair scores, packed f32x2. block=256 (TI x TJ), grid=(1024, B*2).
__global__ __launch_bounds__(256) void k2_scores(float* __restrict__ out) {
    __shared__ float hv_s[TJ * 130];  // even pad: 8B aligned + conflict-free LDS.64
    __shared__ float hd_s[TI * HH];
    __shared__ float wg_s[HH];

    int bh = blockIdx.y;
    int b = bh >> 1, head = bh & 1;
    int iBlk = blockIdx.x >> 4, jBlk = blockIdx.x & 15;
    int i0 = iBlk * TI, j0 = jBlk * TJ;

    const float* hv = g_proj[head * 2 + 0] + b * SS * HH;
    const float* hd = g_proj[head * 2 + 1] + b * SS * HH;

    int tid = threadIdx.x;
    if (tid < HH) wg_s[tid] = g_wg[head][tid];
    for (int idx = tid; idx < TI * HH; idx += 256) hd_s[idx] = hd[i0 * HH + idx];
    for (int idx = tid; idx < TJ * HH; idx += 256) {
        int r = idx >> 7, c = idx & 127;
        hv_s[r * 130 + c] = hv[(j0 + r) * HH + c];
    }
    __syncthreads();

    int jl = tid & 31, il = tid >> 5;
    const ull* hdp = (const ull*)&hd_s[il * HH];
    const ull* hvp = (const ull*)&hv_s[jl * 130];
    const ull* wgp = (const ull*)wg_s;

    const ull cA = pk(0.7978845608f * 0.044715f, 0.7978845608f * 0.044715f);
    const ull cB = pk(0.7978845608f, 0.7978845608f);
    const ull cH = pk(0.5f, 0.5f);

    ull s0 = 0ull, s1 = 0ull, sd = 0ull;
#pragma unroll 8
    for (int hh = 0; hh < HH / 2; hh++) {
        ull x  = add2(hdp[hh], hvp[hh]);
        ull x2 = mul2(x, x);
        ull u  = mul2(x, fma2(cA, x2, cB));
        float ulo, uhi; upk(u, ulo, uhi);
        ull t  = pk(tanh_fast(ulo), tanh_fast(uhi));
        ull xh = mul2(x, cH);
        ull g  = fma2(xh, t, xh);
        s0 = add2(s0, g);
        s1 = fma2(g, g, s1);
        sd = fma2(wgp[hh], g, sd);
    }
    float a0, a1, b0, b1, d0, d1;
    upk(s0, a0, a1); upk(s1, b0, b1); upk(sd, d0, d1);
    float fs0 = a0 + a1, fs1 = b0 + b1, fsd = d0 + d1;

    float m = fs0 * (1.0f / HH);
    float var = fs1 * (1.0f / HH) - m * m;
    float rstd = rsqrtf(var + EPSF);
    float score = fmaf(rstd, fsd - m * g_c[head][0], g_c[head][1]);

    out[BB * SS * AA + head * (BB * SS * SS) + b * (SS * SS) + (i0 + il) * SS + (j0 + jl)] = score;
}

// K3: in-place log-softmax over last dim (512), float4 per thread.
__global__ __launch_bounds__(128) void k3_lsm_rows(float* __restrict__ out) {
    __shared__ float red[4];
    int row = blockIdx.x;
    float4* p = (float4*)(out + BB * SS * AA + row * SS);
    int tid = threadIdx.x;
    float4 v = p[tid];
    float mx = fmaxf(fmaxf(v.x, v.y), fmaxf(v.z, v.w));
    mx = blockMax128(mx, red);
    float s = __expf(v.x - mx) + __expf(v.y - mx) + __expf(v.z - mx) + __expf(v.w - mx);
    s = blockSum128(s, red);
    float l = mx + __logf(s);
    v.x -= l; v.y -= l; v.z -= l; v.w -= l;
    p[tid] = v;
}

// K4: actions log-softmax over the sequence dim. One block per (b, a).
__global__ __launch_bounds__(128) void k4_actions(float* __restrict__ out) {
    __shared__ float red[4];
    int ba = blockIdx.x;
    int b = ba / AA, a = ba % AA;
    const float* lg = g_logits + b * SS * AA + a;
    int tid = threadIdx.x;
    float v[4];
    float mx = -INFINITY;
#pragma unroll
    for (int k = 0; k < 4; k++) {
        v[k] = lg[(tid + k * 128) * AA];
        mx = fmaxf(mx, v[k]);
    }
    mx = blockMax128(mx, red);
    float s = 0.f;
#pragma unroll
    for (int k = 0; k < 4; k++) s += __expf(v[k] - mx);
    s = blockSum128(s, red);
    float l = mx + __logf(s);
    float* o = out + b * SS * AA + a;
#pragma unroll
    for (int k = 0; k < 4; k++) o[(tid + k * 128) * AA] = v[k] - l;
}

extern "C" void kernel_launch(void* const* d_in, const int* in_sizes, int n_in,
                              void* d_out, int out_size) {
    const float* hiddens = (const float*)d_in[0];
    const float* aw1     = (const float*)d_in[1];
    const float* ab1     = (const float*)d_in[2];
    const float* a_ln_g  = (const float*)d_in[3];
    const float* a_ln_b  = (const float*)d_in[4];
    const float* aw2     = (const float*)d_in[5];
    const float* ab2     = (const float*)d_in[6];
    const float* lhid_w  = (const float*)d_in[7];
    const float* lhid_b  = (const float*)d_in[8];
    const float* lhead_w = (const float*)d_in[9];
    const float* lhead_b = (const float*)d_in[10];
    const float* l_ln_g  = (const float*)d_in[11];
    const float* l_ln_b  = (const float*)d_in[12];
    const float* l_proj_w = (const float*)d_in[13];
    const float* l_proj_b = (const float*)d_in[14];
    const float* rhid_w  = (const float*)d_in[15];
    const float* rhid_b  = (const float*)d_in[16];
    const float* rhead_w = (const float*)d_in[17];
    const float* rhead_b = (const float*)d_in[18];
    const float* r_ln_g  = (const float*)d_in[19];
    const float* r_ln_b  = (const float*)d_in[20];
    const float* r_proj_w = (const float*)d_in[21];
    const float* r_proj_b = (const float*)d_in[22];
    float* out = (float*)d_out;

    k0_prep<<<2, 128>>>(l_proj_w, l_ln_g, l_ln_b, l_proj_b,
                        r_proj_w, r_ln_g, r_ln_b, r_proj_b);
    k1a_proj<<<dim3(BB * SS / T1, 5), 128>>>(hiddens,
        lhid_w, lhid_b, lhead_w, lhead_b, rhid_w, rhid_b, rhead_w, rhead_b, aw1, ab1);
    k1b_action<<<BB * SS, 128>>>(a_ln_g, a_ln_b, aw2, ab2);
    k2_scores<<<dim3(1024, BB * 2), 256>>>(out);
    k3_lsm_rows<<<2 * BB * SS, 128>>>(out);
    k4_actions<<<BB * AA, 128>>>(out);
}

// round 4
// speedup vs baseline: 1.3604x; 1.1419x over previous
#include <cuda_runtime.h>
#include <math.h>

#define BB 2
#define SS 512
#define HH 128
#define AA 7
#define T1 16
#define EPSF 1e-5f

typedef unsigned long long ull;

// Scratch
__device__ float g_proj[4][BB * SS * HH];
__device__ float g_act[BB * SS * HH];
__device__ float g_logits[BB * SS * AA];
__device__ float g_wg[2][HH];
__device__ float g_c[2][2];

// ---------------- packed f32x2 helpers (sm_103a) ----------------
__device__ __forceinline__ ull pk(float lo, float hi) {
    ull r; asm("mov.b64 %0, {%1, %2};" : "=l"(r) : "f"(lo), "f"(hi)); return r;
}
__device__ __forceinline__ void upk(ull v, float& lo, float& hi) {
    asm("mov.b64 {%0, %1}, %2;" : "=f"(lo), "=f"(hi) : "l"(v));
}
__device__ __forceinline__ ull add2(ull a, ull b) {
    ull r; asm("add.rn.f32x2 %0, %1, %2;" : "=l"(r) : "l"(a), "l"(b)); return r;
}
__device__ __forceinline__ ull mul2(ull a, ull b) {
    ull r; asm("mul.rn.f32x2 %0, %1, %2;" : "=l"(r) : "l"(a), "l"(b)); return r;
}
__device__ __forceinline__ ull fma2(ull a, ull b, ull c) {
    ull r; asm("fma.rn.f32x2 %0, %1, %2, %3;" : "=l"(r) : "l"(a), "l"(b), "l"(c)); return r;
}

__device__ __forceinline__ float tanh_fast(float x) {
    float y; asm("tanh.approx.f32 %0, %1;" : "=f"(y) : "f"(x)); return y;
}
__device__ __forceinline__ float gelu_t(float x) {
    float x2 = x * x;
    float u = x * fmaf(0.7978845608f * 0.044715f, x2, 0.7978845608f);
    float t = tanh_fast(u);
    float xh = 0.5f * x;
    return fmaf(xh, t, xh);
}

// ---------------- block reductions (blockDim.x == 128) ----------------
__device__ __forceinline__ float blockSum128(float v, float* red) {
#pragma unroll
    for (int o = 16; o; o >>= 1) v += __shfl_xor_sync(0xffffffffu, v, o);
    __syncthreads();
    if ((threadIdx.x & 31) == 0) red[threadIdx.x >> 5] = v;
    __syncthreads();
    return red[0] + red[1] + red[2] + red[3];
}
__device__ __forceinline__ float blockMax128(float v, float* red) {
#pragma unroll
    for (int o = 16; o; o >>= 1) v = fmaxf(v, __shfl_xor_sync(0xffffffffu, v, o));
    __syncthreads();
    if ((threadIdx.x & 31) == 0) red[threadIdx.x >> 5] = v;
    __syncthreads();
    return fmaxf(fmaxf(red[0], red[1]), fmaxf(red[2], red[3]));
}

// K0: fold proj vector + LN affine into wg / constants.
__global__ void k0_prep(const float* lpw, const float* lg, const float* lb, const float* lpb,
                        const float* rpw, const float* rg, const float* rb, const float* rpb) {
    __shared__ float red[4];
    int head = blockIdx.x;
    const float* pw = head ? rpw : lpw;
    const float* g  = head ? rg  : lg;
    const float* bb = head ? rb  : lb;
    const float* pb = head ? rpb : lpb;
    int h = threadIdx.x;
    float w = pw[h];
    float wg = w * g[h];
    g_wg[head][h] = wg;
    float c1 = blockSum128(wg, red);
    float c2 = blockSum128(w * bb[h], red);
    if (h == 0) { g_c[head][0] = c1; g_c[head][1] = c2 + pb[0]; }
}

// K1a: tiled projections, f32x2 accumulators. grid=(64, 5).
__global__ __launch_bounds__(128) void k1a_proj(
        const float* __restrict__ hid,
        const float* __restrict__ w0, const float* __restrict__ b0,
        const float* __restrict__ w1, const float* __restrict__ b1,
        const float* __restrict__ w2, const float* __restrict__ b2,
        const float* __restrict__ w3, const float* __restrict__ b3,
        const float* __restrict__ w4, const float* __restrict__ b4) {
    __shared__ float sh[HH * 20];  // transposed [h][token], stride 20
    int m = blockIdx.y;
    const float* W; const float* B; float* O;
    if      (m == 0) { W = w0; B = b0; O = g_proj[0]; }
    else if (m == 1) { W = w1; B = b1; O = g_proj[1]; }
    else if (m == 2) { W = w2; B = b2; O = g_proj[2]; }
    else if (m == 3) { W = w3; B = b3; O = g_proj[3]; }
    else             { W = w4; B = b4; O = g_act; }

    int t0 = blockIdx.x * T1;
    int tid = threadIdx.x;
    for (int idx = tid; idx < T1 * HH; idx += 128) {
        int t = idx >> 7, c = idx & 127;
        sh[c * 20 + t] = hid[(t0 + t) * HH + c];
    }
    __syncthreads();

    int j = tid;
    float bj = B[j];
    ull acc[T1 / 2];
    ull bj2 = pk(bj, bj);
#pragma unroll
    for (int q = 0; q < T1 / 2; q++) acc[q] = bj2;

#pragma unroll 4
    for (int k = 0; k < HH; k++) {
        float w = W[k * HH + j];
        ull wv = pk(w, w);
        const ull* hp = (const ull*)&sh[k * 20];
#pragma unroll
        for (int q = 0; q < T1 / 2; q++) acc[q] = fma2(hp[q], wv, acc[q]);
    }
#pragma unroll
    for (int q = 0; q < T1 / 2; q++) {
        float lo, hi; upk(acc[q], lo, hi);
        O[(t0 + 2 * q) * HH + j] = lo;
        O[(t0 + 2 * q + 1) * HH + j] = hi;
    }
}

// K1b: action tail: gelu -> LN -> 7 logits. One block per token.
__global__ __launch_bounds__(128) void k1b_action(
        const float* __restrict__ alg, const float* __restrict__ alb,
        const float* __restrict__ aw2, const float* __restrict__ ab2) {
    __shared__ float sa[HH];
    __shared__ float red[4];
    int t = blockIdx.x;
    int tid = threadIdx.x;
    float x = gelu_t(g_act[t * HH + tid]);
    float s0 = blockSum128(x, red);
    float s1 = blockSum128(x * x, red);
    float m = s0 * (1.0f / HH);
    float var = s1 * (1.0f / HH) - m * m;
    float rstd = rsqrtf(var + EPSF);
    sa[tid] = fmaf((x - m) * rstd, alg[tid], alb[tid]);
    __syncthreads();

    int w = tid >> 5, l = tid & 31;
    for (int a = w; a < AA; a += 4) {
        float s = 0.f;
#pragma unroll
        for (int q = 0; q < 4; q++) {
            int jj = l + 32 * q;
            s = fmaf(sa[jj], aw2[jj * AA + a], s);
        }
#pragma unroll
        for (int o = 16; o; o >>= 1) s += __shfl_xor_sync(0xffffffffu, s, o);
        if (l == 0) g_logits[t * AA + a] = s + ab2[a];
    }
}

// K2: pointer pair scores. IR=4 register tile per thread.
// block = 256 threads = 8 warps. Warp w handles i-rows [i0+4w, i0+4w+4), lanes = j.
// Tile: 32 i x 32 j. grid = (16*16, B*2).
__global__ __launch_bounds__(256) void k2_scores(float* __restrict__ out) {
    __shared__ float hd_s[32 * HH];     // [i][h], loop reads are warp-broadcast
    __shared__ float2 hv_s[64 * 33];    // [hh][j], row stride 33 float2 (conflict-free)
    __shared__ float wg_s[HH];

    int bh = blockIdx.y;
    int b = bh >> 1, head = bh & 1;
    int iBlk = blockIdx.x >> 4, jBlk = blockIdx.x & 15;
    int i0 = iBlk * 32, j0 = jBlk * 32;

    const float* hv = g_proj[head * 2 + 0] + b * SS * HH;
    const float* hd = g_proj[head * 2 + 1] + b * SS * HH;

    int tid = threadIdx.x;
    if (tid < HH) wg_s[tid] = g_wg[head][tid];

    // hd tile: direct float4 copy of 32 rows
    {
        const float4* src = (const float4*)(hd + i0 * HH);
        float4* dst = (float4*)hd_s;
        for (int k = tid; k < 32 * HH / 4; k += 256) dst[k] = src[k];
    }
    // hv tile: transpose into [hh][j] float2 rows
    {
        int j = tid >> 3;       // 0..31
        int cg = tid & 7;       // 0..7 -> columns cg*16 .. cg*16+15
        const float4* src = (const float4*)(hv + (j0 + j) * HH + cg * 16);
#pragma unroll
        for (int q = 0; q < 4; q++) {
            float4 v = src[q];
            int hh = cg * 8 + q * 2;
            hv_s[hh * 33 + j] = make_float2(v.x, v.y);
            hv_s[(hh + 1) * 33 + j] = make_float2(v.z, v.w);
        }
    }
    __syncthreads();

    int jl = tid & 31;
    int ib = (tid >> 5) * 4;   // warp's i base within tile

    const ull* hd0 = (const ull*)&hd_s[(ib + 0) * HH];
    const ull* hd1 = (const ull*)&hd_s[(ib + 1) * HH];
    const ull* hd2 = (const ull*)&hd_s[(ib + 2) * HH];
    const ull* hd3 = (const ull*)&hd_s[(ib + 3) * HH];
    const ull* wgp = (const ull*)wg_s;
    const ull* hvp = (const ull*)hv_s + jl;   // element [hh] at hvp[hh*33]

    const ull cA = pk(0.7978845608f * 0.044715f, 0.7978845608f * 0.044715f);
    const ull cB = pk(0.7978845608f, 0.7978845608f);

    // accumulate y = 2*gelu(x):  y = x + x*tanh(u)
    ull s0[4], s1[4], sd[4];
#pragma unroll
    for (int i = 0; i < 4; i++) { s0[i] = 0ull; s1[i] = 0ull; sd[i] = 0ull; }

#pragma unroll 2
    for (int hh = 0; hh < HH / 2; hh++) {
        ull hvv = hvp[hh * 33];
        ull wgv = wgp[hh];
        ull hdv[4] = { hd0[hh], hd1[hh], hd2[hh], hd3[hh] };
#pragma unroll
        for (int i = 0; i < 4; i++) {
            ull x  = add2(hdv[i], hvv);
            ull x2 = mul2(x, x);
            ull u  = mul2(x, fma2(cA, x2, cB));
            float ulo, uhi; upk(u, ulo, uhi);
            ull t  = pk(tanh_fast(ulo), tanh_fast(uhi));
            ull y  = fma2(x, t, x);
            s0[i] = add2(s0[i], y);
            s1[i] = fma2(y, y, s1[i]);
            sd[i] = fma2(wgv, y, sd[i]);
        }
    }

    float c1 = g_c[head][0], c2 = g_c[head][1];
    float* op = out + BB * SS * AA + head * (BB * SS * SS) + b * (SS * SS)
              + (i0 + ib) * SS + (j0 + jl);
#pragma unroll
    for (int i = 0; i < 4; i++) {
        float a0, a1, q0, q1, d0, d1;
        upk(s0[i], a0, a1); upk(s1[i], q0, q1); upk(sd[i], d0, d1);
        float fs0 = a0 + a1, fs1 = q0 + q1, fsd = d0 + d1;
        float m   = fs0 * (1.0f / (2.0f * HH));
        float eg2 = fs1 * (1.0f / (4.0f * HH));
        float var = eg2 - m * m;
        float rstd = rsqrtf(var + EPSF);
        float score = fmaf(rstd, fmaf(-m, c1, 0.5f * fsd), c2);
        op[i * SS] = score;
    }
}

// K3: in-place log-softmax over last dim (512), float4 per thread.
__global__ __launch_bounds__(128) void k3_lsm_rows(float* __restrict__ out) {
    __shared__ float red[4];
    int row = blockIdx.x;
    float4* p = (float4*)(out + BB * SS * AA + row * SS);
    int tid = threadIdx.x;
    float4 v = p[tid];
    float mx = fmaxf(fmaxf(v.x, v.y), fmaxf(v.z, v.w));
    mx = blockMax128(mx, red);
    float s = __expf(v.x - mx) + __expf(v.y - mx) + __expf(v.z - mx) + __expf(v.w - mx);
    s = blockSum128(s, red);
    float l = mx + __logf(s);
    v.x -= l; v.y -= l; v.z -= l; v.w -= l;
    p[tid] = v;
}

// K4: actions log-softmax over the sequence dim. One block per (b, a).
__global__ __launch_bounds__(128) void k4_actions(float* __restrict__ out) {
    __shared__ float red[4];
    int ba = blockIdx.x;
    int b = ba / AA, a = ba % AA;
    const float* lg = g_logits + b * SS * AA + a;
    int tid = threadIdx.x;
    float v[4];
    float mx = -INFINITY;
#pragma unroll
    for (int k = 0; k < 4; k++) {
        v[k] = lg[(tid + k * 128) * AA];
        mx = fmaxf(mx, v[k]);
    }
    mx = blockMax128(mx, red);
    float s = 0.f;
#pragma unroll
    for (int k = 0; k < 4; k++) s += __expf(v[k] - mx);
    s = blockSum128(s, red);
    float l = mx + __logf(s);
    float* o = out + b * SS * AA + a;
#pragma unroll
    for (int k = 0; k < 4; k++) o[(tid + k * 128) * AA] = v[k] - l;
}

extern "C" void kernel_launch(void* const* d_in, const int* in_sizes, int n_in,
                              void* d_out, int out_size) {
    const float* hiddens = (const float*)d_in[0];
    const float* aw1     = (const float*)d_in[1];
    const float* ab1     = (const float*)d_in[2];
    const float* a_ln_g  = (const float*)d_in[3];
    const float* a_ln_b  = (const float*)d_in[4];
    const float* aw2     = (const float*)d_in[5];
    const float* ab2     = (const float*)d_in[6];
    const float* lhid_w  = (const float*)d_in[7];
    const float* lhid_b  = (const float*)d_in[8];
    const float* lhead_w = (const float*)d_in[9];
    const float* lhead_b = (const float*)d_in[10];
    const float* l_ln_g  = (const float*)d_in[11];
    const float* l_ln_b  = (const float*)d_in[12];
    const float* l_proj_w = (const float*)d_in[13];
    const float* l_proj_b = (const float*)d_in[14];
    const float* rhid_w  = (const float*)d_in[15];
    const float* rhid_b  = (const float*)d_in[16];
    const float* rhead_w = (const float*)d_in[17];
    const float* rhead_b = (const float*)d_in[18];
    const float* r_ln_g  = (const float*)d_in[19];
    const float* r_ln_b  = (const float*)d_in[20];
    const float* r_proj_w = (const float*)d_in[21];
    const float* r_proj_b = (const float*)d_in[22];
    float* out = (float*)d_out;

    k0_prep<<<2, 128>>>(l_proj_w, l_ln_g, l_ln_b, l_proj_b,
                        r_proj_w, r_ln_g, r_ln_b, r_proj_b);
    k1a_proj<<<dim3(BB * SS / T1, 5), 128>>>(hiddens,
        lhid_w, lhid_b, lhead_w, lhead_b, rhid_w, rhid_b, rhead_w, rhead_b, aw1, ab1);
    k1b_action<<<BB * SS, 128>>>(a_ln_g, a_ln_b, aw2, ab2);
    k2_scores<<<dim3(16 * 16, BB * 2), 256>>>(out);
    k3_lsm_rows<<<2 * BB * SS, 128>>>(out);
    k4_actions<<<BB * AA, 128>>>(out);
}

// round 5
// speedup vs baseline: 1.4088x; 1.0355x over previous
#include <cuda_runtime.h>
#include <math.h>

#define BB 2
#define SS 512
#define HH 128
#define AA 7
#define T1 16
#define EPSF 1e-5f
#define NTILES 1024

typedef unsigned long long ull;

// Scratch
__device__ float g_proj[4][BB * SS * HH];
__device__ float g_act[BB * SS * HH];
__device__ float g_logits[BB * SS * AA];
__device__ float g_wg[2][HH];
__device__ float g_c[2][2];
__device__ unsigned int g_tile_ctr;

// ---------------- packed f32x2 helpers (sm_103a) ----------------
__device__ __forceinline__ ull pk(float lo, float hi) {
    ull r; asm("mov.b64 %0, {%1, %2};" : "=l"(r) : "f"(lo), "f"(hi)); return r;
}
__device__ __forceinline__ void upk(ull v, float& lo, float& hi) {
    asm("mov.b64 {%0, %1}, %2;" : "=f"(lo), "=f"(hi) : "l"(v));
}
__device__ __forceinline__ ull add2(ull a, ull b) {
    ull r; asm("add.rn.f32x2 %0, %1, %2;" : "=l"(r) : "l"(a), "l"(b)); return r;
}
__device__ __forceinline__ ull mul2(ull a, ull b) {
    ull r; asm("mul.rn.f32x2 %0, %1, %2;" : "=l"(r) : "l"(a), "l"(b)); return r;
}
__device__ __forceinline__ ull fma2(ull a, ull b, ull c) {
    ull r; asm("fma.rn.f32x2 %0, %1, %2, %3;" : "=l"(r) : "l"(a), "l"(b), "l"(c)); return r;
}

__device__ __forceinline__ float tanh_fast(float x) {
    float y; asm("tanh.approx.f32 %0, %1;" : "=f"(y) : "f"(x)); return y;
}
__device__ __forceinline__ float gelu_t(float x) {
    float x2 = x * x;
    float u = x * fmaf(0.7978845608f * 0.044715f, x2, 0.7978845608f);
    float t = tanh_fast(u);
    float xh = 0.5f * x;
    return fmaf(xh, t, xh);
}

// ---------------- block reductions (blockDim.x == 128) ----------------
__device__ __forceinline__ float blockSum128(float v, float* red) {
#pragma unroll
    for (int o = 16; o; o >>= 1) v += __shfl_xor_sync(0xffffffffu, v, o);
    __syncthreads();
    if ((threadIdx.x & 31) == 0) red[threadIdx.x >> 5] = v;
    __syncthreads();
    return red[0] + red[1] + red[2] + red[3];
}
__device__ __forceinline__ float blockMax128(float v, float* red) {
#pragma unroll
    for (int o = 16; o; o >>= 1) v = fmaxf(v, __shfl_xor_sync(0xffffffffu, v, o));
    __syncthreads();
    if ((threadIdx.x & 31) == 0) red[threadIdx.x >> 5] = v;
    __syncthreads();
    return fmaxf(fmaxf(red[0], red[1]), fmaxf(red[2], red[3]));
}

// kA: tiled projections (k1a) + [block (0,0) only] k0 prep + tile-counter reset.
// grid = (64, 5), block = 128.
__global__ __launch_bounds__(128) void kA_proj(
        const float* __restrict__ hid,
        const float* __restrict__ w0, const float* __restrict__ b0,
        const float* __restrict__ w1, const float* __restrict__ b1,
        const float* __restrict__ w2, const float* __restrict__ b2,
        const float* __restrict__ w3, const float* __restrict__ b3,
        const float* __restrict__ w4, const float* __restrict__ b4,
        const float* __restrict__ lpw, const float* __restrict__ lg,
        const float* __restrict__ lb,  const float* __restrict__ lpb,
        const float* __restrict__ rpw, const float* __restrict__ rg,
        const float* __restrict__ rb,  const float* __restrict__ rpb) {
    __shared__ float sh[HH * 20];  // transposed [h][token], stride 20
    __shared__ float red[4];
    int m = blockIdx.y;
    int tid = threadIdx.x;

    // --- prep (one block only) ---
    if (m == 0 && blockIdx.x == 0) {
        if (tid == 0) g_tile_ctr = 0u;
#pragma unroll
        for (int head = 0; head < 2; head++) {
            const float* pw = head ? rpw : lpw;
            const float* gg = head ? rg  : lg;
            const float* bv = head ? rb  : lb;
            const float* pb = head ? rpb : lpb;
            float w = pw[tid];
            float wg = w * gg[tid];
            g_wg[head][tid] = wg;
            float c1 = blockSum128(wg, red);
            float c2 = blockSum128(w * bv[tid], red);
            if (tid == 0) { g_c[head][0] = c1; g_c[head][1] = c2 + pb[0]; }
        }
        __syncthreads();
    }

    const float* W; const float* B; float* O;
    if      (m == 0) { W = w0; B = b0; O = g_proj[0]; }
    else if (m == 1) { W = w1; B = b1; O = g_proj[1]; }
    else if (m == 2) { W = w2; B = b2; O = g_proj[2]; }
    else if (m == 3) { W = w3; B = b3; O = g_proj[3]; }
    else             { W = w4; B = b4; O = g_act; }

    int t0 = blockIdx.x * T1;
    for (int idx = tid; idx < T1 * HH; idx += 128) {
        int t = idx >> 7, c = idx & 127;
        sh[c * 20 + t] = hid[(t0 + t) * HH + c];
    }
    __syncthreads();

    int j = tid;
    float bj = B[j];
    ull acc[T1 / 2];
    ull bj2 = pk(bj, bj);
#pragma unroll
    for (int q = 0; q < T1 / 2; q++) acc[q] = bj2;

#pragma unroll 4
    for (int k = 0; k < HH; k++) {
        float w = W[k * HH + j];
        ull wv = pk(w, w);
        const ull* hp = (const ull*)&sh[k * 20];
#pragma unroll
        for (int q = 0; q < T1 / 2; q++) acc[q] = fma2(hp[q], wv, acc[q]);
    }
#pragma unroll
    for (int q = 0; q < T1 / 2; q++) {
        float lo, hi; upk(acc[q], lo, hi);
        O[(t0 + 2 * q) * HH + j] = lo;
        O[(t0 + 2 * q + 1) * HH + j] = hi;
    }
}

// kB: action tail: gelu -> LN -> 7 logits. One block per token.
__global__ __launch_bounds__(128) void kB_action(
        const float* __restrict__ alg, const float* __restrict__ alb,
        const float* __restrict__ aw2, const float* __restrict__ ab2) {
    __shared__ float sa[HH];
    __shared__ float red[4];
    int t = blockIdx.x;
    int tid = threadIdx.x;
    float x = gelu_t(g_act[t * HH + tid]);
    float s0 = blockSum128(x, red);
    float s1 = blockSum128(x * x, red);
    float m = s0 * (1.0f / HH);
    float var = s1 * (1.0f / HH) - m * m;
    float rstd = rsqrtf(var + EPSF);
    sa[tid] = fmaf((x - m) * rstd, alg[tid], alb[tid]);
    __syncthreads();

    int w = tid >> 5, l = tid & 31;
    for (int a = w; a < AA; a += 4) {
        float s = 0.f;
#pragma unroll
        for (int q = 0; q < 4; q++) {
            int jj = l + 32 * q;
            s = fmaf(sa[jj], aw2[jj * AA + a], s);
        }
#pragma unroll
        for (int o = 16; o; o >>= 1) s += __shfl_xor_sync(0xffffffffu, s, o);
        if (l == 0) g_logits[t * AA + a] = s + ab2[a];
    }
}

// k2: pointer pair scores. Persistent blocks + dynamic tile counter.
// grid = 592 (4 blocks/SM), block = 256 = 8 warps. Tile = 32i x 32j, IR=4.
__global__ __launch_bounds__(256) void k2_scores(float* __restrict__ out) {
    __shared__ float hd_s[32 * HH];     // [i][h], loop reads are warp-broadcast
    __shared__ float2 hv_s[64 * 33];    // [hh][j], row stride 33 float2
    __shared__ float wg_s[2][HH];
    __shared__ unsigned int s_tile;

    int tid = threadIdx.x;
    if (tid < HH) { wg_s[0][tid] = g_wg[0][tid]; wg_s[1][tid] = g_wg[1][tid]; }

    const ull cA = pk(0.7978845608f * 0.044715f, 0.7978845608f * 0.044715f);
    const ull cB = pk(0.7978845608f, 0.7978845608f);

    int jl = tid & 31;
    int ib = (tid >> 5) * 4;

    while (true) {
        if (tid == 0) s_tile = atomicAdd(&g_tile_ctr, 1u);
        __syncthreads();               // orders s_tile AND protects smem reuse
        unsigned int tile = s_tile;
        if (tile >= NTILES) break;

        int bh = tile >> 8;
        int b = bh >> 1, head = bh & 1;
        int rest = tile & 255;
        int i0 = (rest >> 4) * 32, j0 = (rest & 15) * 32;

        const float* hv = g_proj[head * 2 + 0] + b * SS * HH;
        const float* hd = g_proj[head * 2 + 1] + b * SS * HH;

        // hd tile: direct float4 copy of 32 rows
        {
            const float4* src = (const float4*)(hd + i0 * HH);
            float4* dst = (float4*)hd_s;
            for (int k = tid; k < 32 * HH / 4; k += 256) dst[k] = src[k];
        }
        // hv tile: transpose into [hh][j] float2 rows
        {
            int j = tid >> 3;
            int cg = tid & 7;
            const float4* src = (const float4*)(hv + (j0 + j) * HH + cg * 16);
#pragma unroll
            for (int q = 0; q < 4; q++) {
                float4 v = src[q];
                int hh = cg * 8 + q * 2;
                hv_s[hh * 33 + j] = make_float2(v.x, v.y);
                hv_s[(hh + 1) * 33 + j] = make_float2(v.z, v.w);
            }
        }
        __syncthreads();

        const ull* hd0 = (const ull*)&hd_s[(ib + 0) * HH];
        const ull* hd1 = (const ull*)&hd_s[(ib + 1) * HH];
        const ull* hd2 = (const ull*)&hd_s[(ib + 2) * HH];
        const ull* hd3 = (const ull*)&hd_s[(ib + 3) * HH];
        const ull* wgp = (const ull*)wg_s[head];
        const ull* hvp = (const ull*)hv_s + jl;

        // accumulate y = 2*gelu(x):  y = x + x*tanh(u)
        ull s0[4], s1[4], sd[4];
#pragma unroll
        for (int i = 0; i < 4; i++) { s0[i] = 0ull; s1[i] = 0ull; sd[i] = 0ull; }

#pragma unroll 4
        for (int hh = 0; hh < HH / 2; hh++) {
            ull hvv = hvp[hh * 33];
            ull wgv = wgp[hh];
            ull hdv[4] = { hd0[hh], hd1[hh], hd2[hh], hd3[hh] };
#pragma unroll
            for (int i = 0; i < 4; i++) {
                ull x  = add2(hdv[i], hvv);
                ull x2 = mul2(x, x);
                ull u  = mul2(x, fma2(cA, x2, cB));
                float ulo, uhi; upk(u, ulo, uhi);
                ull t  = pk(tanh_fast(ulo), tanh_fast(uhi));
                ull y  = fma2(x, t, x);
                s0[i] = add2(s0[i], y);
                s1[i] = fma2(y, y, s1[i]);
                sd[i] = fma2(wgv, y, sd[i]);
            }
        }

        float c1 = g_c[head][0], c2 = g_c[head][1];
        float* op = out + BB * SS * AA + head * (BB * SS * SS) + b * (SS * SS)
                  + (i0 + ib) * SS + (j0 + jl);
#pragma unroll
        for (int i = 0; i < 4; i++) {
            float a0, a1, q0, q1, d0, d1;
            upk(s0[i], a0, a1); upk(s1[i], q0, q1); upk(sd[i], d0, d1);
            float fs0 = a0 + a1, fs1 = q0 + q1, fsd = d0 + d1;
            float m    = fs0 * (1.0f / (2.0f * HH));
            float eg2  = fs1 * (1.0f / (4.0f * HH));
            float var  = eg2 - m * m;
            float rstd = rsqrtf(var + EPSF);
            float score = fmaf(rstd, fmaf(-m, c1, 0.5f * fsd), c2);
            op[i * SS] = score;
        }
    }
}

// kD: merged log-softmaxes. blocks [0, 2048) = pointer rows (dim 512),
// blocks [2048, 2062) = action columns over sequence dim.
__global__ __launch_bounds__(128) void kD_lsm(float* __restrict__ out) {
    __shared__ float red[4];
    int blk = blockIdx.x;
    int tid = threadIdx.x;
    if (blk < 2 * BB * SS) {
        float4* p = (float4*)(out + BB * SS * AA + blk * SS);
        float4 v = p[tid];
        float mx = fmaxf(fmaxf(v.x, v.y), fmaxf(v.z, v.w));
        mx = blockMax128(mx, red);
        float s = __expf(v.x - mx) + __expf(v.y - mx) + __expf(v.z - mx) + __expf(v.w - mx);
        s = blockSum128(s, red);
        float l = mx + __logf(s);
        v.x -= l; v.y -= l; v.z -= l; v.w -= l;
        p[tid] = v;
    } else {
        int ba = blk - 2 * BB * SS;
        int b = ba / AA, a = ba % AA;
        const float* lg2 = g_logits + b * SS * AA + a;
        float v[4];
        float mx = -INFINITY;
#pragma unroll
        for (int k = 0; k < 4; k++) {
            v[k] = lg2[(tid + k * 128) * AA];
            mx = fmaxf(mx, v[k]);
        }
        mx = blockMax128(mx, red);
        float s = 0.f;
#pragma unroll
        for (int k = 0; k < 4; k++) s += __expf(v[k] - mx);
        s = blockSum128(s, red);
        float l = mx + __logf(s);
        float* o = out + b * SS * AA + a;
#pragma unroll
        for (int k = 0; k < 4; k++) o[(tid + k * 128) * AA] = v[k] - l;
    }
}

extern "C" void kernel_launch(void* const* d_in, const int* in_sizes, int n_in,
                              void* d_out, int out_size) {
    const float* hiddens = (const float*)d_in[0];
    const float* aw1     = (const float*)d_in[1];
    const float* ab1     = (const float*)d_in[2];
    const float* a_ln_g  = (const float*)d_in[3];
    const float* a_ln_b  = (const float*)d_in[4];
    const float* aw2     = (const float*)d_in[5];
    const float* ab2     = (const float*)d_in[6];
    const float* lhid_w  = (const float*)d_in[7];
    const float* lhid_b  = (const float*)d_in[8];
    const float* lhead_w = (const float*)d_in[9];
    const float* lhead_b = (const float*)d_in[10];
    const float* l_ln_g  = (const float*)d_in[11];
    const float* l_ln_b  = (const float*)d_in[12];
    const float* l_proj_w = (const float*)d_in[13];
    const float* l_proj_b = (const float*)d_in[14];
    const float* rhid_w  = (const float*)d_in[15];
    const float* rhid_b  = (const float*)d_in[16];
    const float* rhead_w = (const float*)d_in[17];
    const float* rhead_b = (const float*)d_in[18];
    const float* r_ln_g  = (const float*)d_in[19];
    const float* r_ln_b  = (const float*)d_in[20];
    const float* r_proj_w = (const float*)d_in[21];
    const float* r_proj_b = (const float*)d_in[22];
    float* out = (float*)d_out;

    kA_proj<<<dim3(BB * SS / T1, 5), 128>>>(hiddens,
        lhid_w, lhid_b, lhead_w, lhead_b, rhid_w, rhid_b, rhead_w, rhead_b, aw1, ab1,
        l_proj_w, l_ln_g, l_ln_b, l_proj_b, r_proj_w, r_ln_g, r_ln_b, r_proj_b);
    kB_action<<<BB * SS, 128>>>(a_ln_g, a_ln_b, aw2, ab2);
    k2_scores<<<592, 256>>>(out);
    kD_lsm<<<2 * BB * SS + BB * AA, 128>>>(out);
}